// round 16
// baseline (speedup 1.0000x reference)
#include <cuda_runtime.h>
#include <cuda_fp16.h>
#include <cstdint>

// Shapes: B=16, T=128, N=64, Cin=128, Cout=256, K=3, kt=3, groups=8
// Per-CTA (b,n): C[128 t][512 vcol] = X[128x128] @ W[n][vcol][c]^T, split-fp16, 2 K-sections
//   sharing one B image: D = x_hi*W_h + x_lo*W_h  (W_h = fp16(W); dropped x*W_lo ~ 2^-12 rel)
// vcol<256: h2 (pre-conv)   vcol>=256: residual
// g_Wh[n][vcol 512][k 128] fp16.  8 fused chunks (pass = j>>2): pass0 -> hs, pass1 -> regs.
// 512 threads / 16 warps: m0=(w>>2)*32 (2 m16), strip=(w&3) -> private 64-col B ring.
// GEMM uses ONLY per-strip named barriers (bar.sync 4+strip, 128) — strips run decoupled.

#define EPSF 1e-5f
#define HS(t,o) ((t)*256 + (((o) & ~31) | (((o) ^ (t)) & 31)))

__device__ __half g_Wh[64UL * 512 * 128];   // 8.4 MB fp16 weight image

// ---------------- helpers ----------------
__device__ __forceinline__ uint32_t s2u(const void* p) {
    uint32_t a;
    asm("{ .reg .u64 t; cvta.to.shared.u64 t, %1; cvt.u32.u64 %0, t; }" : "=r"(a) : "l"(p));
    return a;
}
__device__ __forceinline__ void ldmA(uint32_t* a, uint32_t addr) {
    asm volatile("ldmatrix.sync.aligned.m8n8.x4.shared.b16 {%0,%1,%2,%3}, [%4];"
                 : "=r"(a[0]), "=r"(a[1]), "=r"(a[2]), "=r"(a[3]) : "r"(addr));
}
__device__ __forceinline__ void ldmB4(uint32_t* q, uint32_t addr) {
    asm volatile("ldmatrix.sync.aligned.m8n8.x4.shared.b16 {%0,%1,%2,%3}, [%4];"
                 : "=r"(q[0]), "=r"(q[1]), "=r"(q[2]), "=r"(q[3]) : "r"(addr));
}
__device__ __forceinline__ void mma16816(float* c, const uint32_t* a, const uint32_t* bq) {
    asm volatile("mma.sync.aligned.m16n8k16.row.col.f32.f16.f16.f32 "
                 "{%0,%1,%2,%3}, {%4,%5,%6,%7}, {%8,%9}, {%0,%1,%2,%3};"
                 : "+f"(c[0]), "+f"(c[1]), "+f"(c[2]), "+f"(c[3])
                 : "r"(a[0]), "r"(a[1]), "r"(a[2]), "r"(a[3]), "r"(bq[0]), "r"(bq[1]));
}
__device__ __forceinline__ void cpa16(uint32_t dst, const void* src) {
    asm volatile("cp.async.cg.shared.global [%0], [%1], 16;"
                 :: "r"(dst), "l"((unsigned long long)__cvta_generic_to_global(src)));
}
#define CPA_COMMIT() asm volatile("cp.async.commit_group;" ::: "memory")
#define CPA_WAIT1()  asm volatile("cp.async.wait_group 1;" ::: "memory")
#define CPA_WAIT0()  asm volatile("cp.async.wait_group 0;" ::: "memory")

__device__ __forceinline__ uint32_t packh(float a, float b) {
    __half2 h = __floats2half2_rn(a, b);   // low half = a
    return *(uint32_t*)&h;
}

// ---------------- K0: build fp16 weight image ----------------
// Weff[n][v][c] = sum_k rowA[k,n]*dw[k,c]*Wpw[v,k*128+c]  (v<256);  Wres[v-256][c] (v>=256)
__global__ void k0_weights(const float* __restrict__ A, const float* __restrict__ dw,
                           const float* __restrict__ Wpw, const float* __restrict__ Wres) {
    int n = blockIdx.x;
    int vBase = blockIdx.y * 256;
    int tid = threadIdx.x;
    __shared__ float rA[3];
    if (tid < 3) {
        const float* Ap = A + (size_t)tid * 4096 + n * 64;
        float s = 0.f;
        #pragma unroll
        for (int m = 0; m < 64; m++) s += Ap[m];
        rA[tid] = s;
    }
    __syncthreads();
    float r0 = rA[0], r1 = rA[1], r2 = rA[2];
    uint32_t* dW = (uint32_t*)g_Wh + (size_t)n * 32768;

    for (int it = 0; it < 64; it++) {
        int idx = tid + it * 256;
        int c2 = idx & 63;
        int v = vBase + (idx >> 6);
        int c = c2 * 2;
        float wa, wb;
        if (v < 256) {
            wa = r0 * dw[c]       * Wpw[(size_t)v * 384 + c]
               + r1 * dw[128 + c] * Wpw[(size_t)v * 384 + 128 + c]
               + r2 * dw[256 + c] * Wpw[(size_t)v * 384 + 256 + c];
            wb = r0 * dw[c + 1]   * Wpw[(size_t)v * 384 + c + 1]
               + r1 * dw[129 + c] * Wpw[(size_t)v * 384 + 129 + c]
               + r2 * dw[257 + c] * Wpw[(size_t)v * 384 + 257 + c];
        } else {
            wa = Wres[(size_t)(v - 256) * 128 + c];
            wb = Wres[(size_t)(v - 256) * 128 + c + 1];
        }
        dW[v * 64 + c2] = packh(wa, wb);
    }
}

// ---------------- K_MAIN ----------------
// Dyn smem (1024-aligned): xhi[32K] | xlo[32K] | B rings 4 strips x (2 x 4KB) = 32K | hs[128K]
__global__ __launch_bounds__(512, 1) void k_main(
    const float* __restrict__ x, const float* __restrict__ Wconv,
    const float* __restrict__ gnw, const float* __restrict__ gnb,
    const float* __restrict__ lnw, const float* __restrict__ lnb,
    float* __restrict__ out)
{
    extern __shared__ char dyn[];
    __shared__ float redS[16], redQ[16], gmean[8], ginv[8];
    uint32_t dynBase = s2u(dyn);
    uint32_t base = (dynBase + 1023u) & ~1023u;
    char* smemc = dyn + (base - dynBase);
    float* hs = (float*)(smemc + 98304);

    int n = blockIdx.x, b = blockIdx.y;
    int tid = threadIdx.x;
    int w = tid >> 5, l = tid & 31;
    int m0 = (w >> 2) * 32;          // warp M origin: 2 m16 tiles
    int strip = w & 3;               // N strip (64 cols), shared by 4 warps
    int n0 = strip * 64;
    int gi = (w >> 2) * 32 + l;      // index within strip group (0..127)
    uint32_t sbase = base + 65536u + (uint32_t)strip * 8192u;   // strip's B ring

#define BARS() asm volatile("bar.sync %0, %1;" :: "r"(4 + strip), "r"(128) : "memory")

    const char* wimg = (const char*)g_Wh + (size_t)n * 131072;   // [512 v][256 B]

    // Per-strip B chunk issue: 64 rows x 64B; dst row lr: (lr>>1)*128+(lr&1)*64,
    // 16B chunk ch at + ((ch ^ ((lr>>1)&3)) << 4).  chunk j: pass p=j>>2, cj=j&3 (k32).
#define ISSUE_CHUNK(j) do {                                                             \
    int p_ = (j) >> 2;                                                                  \
    const char* bsrc_ = wimg + (size_t)(p_ * 256 + n0) * 256 + ((j) & 3) * 64;          \
    uint32_t dstb_ = sbase + (uint32_t)((j) & 1) * 4096u;                               \
    _Pragma("unroll")                                                                   \
    for (int it_ = 0; it_ < 2; it_++) {                                                 \
        int flat_ = gi + it_ * 128;                                                     \
        int ch_ = flat_ & 3, lr_ = flat_ >> 2;                                          \
        uint32_t d_ = dstb_ + (uint32_t)((lr_ >> 1) * 128 + (lr_ & 1) * 64)             \
                      + (uint32_t)(((ch_ ^ ((lr_ >> 1) & 3))) << 4);                    \
        cpa16(d_, bsrc_ + (size_t)lr_ * 256 + ch_ * 16);                                \
    }                                                                                   \
    CPA_COMMIT();                                                                       \
} while (0)

    // Per k16: ldmA(hi) -> 4x ldmB4 -> 16 hi-MMAs -> ldmA(lo) -> 16 lo-MMAs (RAW dist >= 16).
#define COMPUTE_CHUNK(j, acc) do {                                                      \
    uint32_t bbase_ = sbase + (uint32_t)((j) & 1) * 4096u;                              \
    _Pragma("unroll")                                                                   \
    for (int kk_ = 0; kk_ < 2; kk_++) {                                                 \
        int chA_ = ((j) & 3) * 4 + kk_ * 2 + (l >> 4);                                  \
        uint32_t af_[2][4];                                                             \
        _Pragma("unroll")                                                               \
        for (int mt_ = 0; mt_ < 2; mt_++) {                                             \
            int m_ = m0 + mt_ * 16 + (l & 15);                                          \
            ldmA(af_[mt_], base + (uint32_t)m_ * 256u + (uint32_t)((chA_ ^ (m_ & 7)) << 4)); \
        }                                                                               \
        uint32_t q_[4][4];                                                              \
        _Pragma("unroll")                                                               \
        for (int np_ = 0; np_ < 4; np_++) {                                             \
            int r_ = np_ * 16 + ((l >> 4) << 3) + (l & 7);                              \
            int chB_ = kk_ * 2 + ((l >> 3) & 1);                                        \
            ldmB4(q_[np_], bbase_ + (uint32_t)((r_ >> 1) * 128 + (r_ & 1) * 64)         \
                      + (uint32_t)(((chB_ ^ ((r_ >> 1) & 3))) << 4));                   \
        }                                                                               \
        _Pragma("unroll")                                                               \
        for (int np_ = 0; np_ < 4; np_++)                                               \
            _Pragma("unroll")                                                           \
            for (int mt_ = 0; mt_ < 2; mt_++) {                                         \
                mma16816(&(acc)[(mt_ * 8 + np_ * 2) * 4],     af_[mt_], q_[np_]);       \
                mma16816(&(acc)[(mt_ * 8 + np_ * 2 + 1) * 4], af_[mt_], q_[np_] + 2);   \
            }                                                                           \
        _Pragma("unroll")                                                               \
        for (int mt_ = 0; mt_ < 2; mt_++) {                                             \
            int m_ = m0 + mt_ * 16 + (l & 15);                                          \
            ldmA(af_[mt_], base + 32768u + (uint32_t)m_ * 256u + (uint32_t)((chA_ ^ (m_ & 7)) << 4)); \
        }                                                                               \
        _Pragma("unroll")                                                               \
        for (int np_ = 0; np_ < 4; np_++)                                               \
            _Pragma("unroll")                                                           \
            for (int mt_ = 0; mt_ < 2; mt_++) {                                         \
                mma16816(&(acc)[(mt_ * 8 + np_ * 2) * 4],     af_[mt_], q_[np_]);       \
                mma16816(&(acc)[(mt_ * 8 + np_ * 2 + 1) * 4], af_[mt_], q_[np_] + 2);   \
            }                                                                           \
    }                                                                                   \
} while (0)

#define ZERO64(a) { _Pragma("unroll") for (int z_ = 0; z_ < 64; z_++) (a)[z_] = 0.f; }
#define FLUSH_HS(acc) do {                                                              \
    _Pragma("unroll")                                                                   \
    for (int mt_ = 0; mt_ < 2; mt_++)                                                   \
    { _Pragma("unroll")                                                                 \
      for (int nt_ = 0; nt_ < 8; nt_++) {                                               \
        int t_ = m0 + mt_ * 16 + (l >> 2);                                              \
        int o_ = n0 + nt_ * 8 + (l & 3) * 2;                                            \
        int i4_ = (mt_ * 8 + nt_) * 4;                                                  \
        hs[HS(t_, o_)]         = (acc)[i4_ + 0];                                        \
        hs[HS(t_, o_ + 1)]     = (acc)[i4_ + 1];                                        \
        hs[HS(t_ + 8, o_)]     = (acc)[i4_ + 2];                                        \
        hs[HS(t_ + 8, o_ + 1)] = (acc)[i4_ + 3];                                        \
    } }                                                                                 \
} while (0)

    // ---- B chunk 0 in flight first, then x-split (overlapped) ----
    ISSUE_CHUNK(0);

    // ---- load x tile [128 t][128 c], split hi/lo fp16, XOR-swizzled 256B rows ----
    {
        int cq = tid & 31, tr = tid >> 5;  // tr 0..15
        const float* xb = x + (size_t)b * 1048576 + (size_t)n * 128;
        #pragma unroll
        for (int i = 0; i < 8; i++) {
            int t = tr + i * 16;
            float4 v = *(const float4*)(xb + (size_t)t * 8192 + cq * 4);
            float hx = __half2float(__float2half_rn(v.x));
            float hy = __half2float(__float2half_rn(v.y));
            float hz = __half2float(__float2half_rn(v.z));
            float hw = __half2float(__float2half_rn(v.w));
            uint32_t h0 = packh(v.x, v.y), h1 = packh(v.z, v.w);
            uint32_t l0 = packh(v.x - hx, v.y - hy), l1 = packh(v.z - hz, v.w - hw);
            int ch = cq >> 1;
            uint32_t off = (uint32_t)t * 256u + (uint32_t)((ch ^ (t & 7)) << 4) + (uint32_t)((cq & 1) * 8);
            *(uint64_t*)(smemc + off)         = (uint64_t)h0 | ((uint64_t)h1 << 32);
            *(uint64_t*)(smemc + 32768 + off) = (uint64_t)l0 | ((uint64_t)l1 << 32);
        }
    }
    __syncthreads();   // A (xhi/xlo) visible to all warps
    ISSUE_CHUNK(1);

    // ---- fused 8-chunk pipeline: j<4 -> acc (h2), j>=4 -> res (residual) ----
    float accA[64], res[64];
    ZERO64(accA);
    ZERO64(res);
    #pragma unroll
    for (int j = 0; j < 8; j++) {
        if (j < 7) CPA_WAIT1(); else CPA_WAIT0();
        BARS();                         // strip's B chunk j ready
        if (j < 4) COMPUTE_CHUNK(j, accA);
        else       COMPUTE_CHUNK(j, res);
        if (j == 3) FLUSH_HS(accA);     // warp-private hs writes, no barrier needed
        BARS();                         // all strip warps done with buffer (j&1)
        if (j < 6) ISSUE_CHUNK(j + 2);
    }
    __syncthreads();

    // ---- E1: depthwise conv3 over T + GroupNorm. thread = (channel o, t-half h). ----
    {
        int o = tid & 255, h = tid >> 8, t0 = h * 64;
        float cw0 = Wconv[o * 3], cw1 = Wconv[o * 3 + 1], cw2 = Wconv[o * 3 + 2];
        float lf = (t0 > 0) ? hs[HS(t0 - 1, o)] : 0.f;
        float endrt = (t0 + 64 < 128) ? hs[HS(t0 + 64, o)] : 0.f;
        float cur = hs[HS(t0, o)];
        __syncthreads();
        float s = 0.f, q = 0.f;
        #pragma unroll 4
        for (int i = 0; i < 64; i++) {
            int t = t0 + i;
            float rt = (i < 63) ? hs[HS(t + 1, o)] : endrt;
            float val = fmaf(cw0, lf, fmaf(cw1, cur, cw2 * rt));
            hs[HS(t, o)] = val;
            s += val;
            q = fmaf(val, val, q);
            lf = cur; cur = rt;
        }
        #pragma unroll
        for (int off = 16; off; off >>= 1) {
            s += __shfl_xor_sync(0xFFFFFFFFu, s, off);
            q += __shfl_xor_sync(0xFFFFFFFFu, q, off);
        }
        if (l == 0) { redS[w] = s; redQ[w] = q; }
        __syncthreads();
        if (tid < 8) {
            float S2 = redS[tid] + redS[tid + 8];
            float Q2 = redQ[tid] + redQ[tid + 8];
            float mean = S2 * (1.f / 4096.f);
            float var = Q2 * (1.f / 4096.f) - mean * mean;
            gmean[tid] = mean;
            ginv[tid] = rsqrtf(var + EPSF);
        }
        __syncthreads();
        int g = o >> 5;
        float sc = ginv[g] * gnw[o];
        float sb = gnb[o] - gmean[g] * sc;
        #pragma unroll 4
        for (int i = 0; i < 64; i++) {
            int t = t0 + i;
            hs[HS(t, o)] = fmaf(hs[HS(t, o)], sc, sb);
        }
    }
    __syncthreads();

    // ---- E2: add residual from registers ----
    #pragma unroll
    for (int mt = 0; mt < 2; mt++)
        #pragma unroll
        for (int nt = 0; nt < 8; nt++) {
            int t = m0 + mt * 16 + (l >> 2);
            int o = n0 + nt * 8 + (l & 3) * 2;
            int i4 = (mt * 8 + nt) * 4;
            hs[HS(t, o)]         += res[i4 + 0];
            hs[HS(t, o + 1)]     += res[i4 + 1];
            hs[HS(t + 8, o)]     += res[i4 + 2];
            hs[HS(t + 8, o + 1)] += res[i4 + 3];
        }
    __syncthreads();

    // ---- E3: LayerNorm over 256 channels per t-row + exact GELU + coalesced store ----
    {
        float lw[8], lb[8];
        #pragma unroll
        for (int j = 0; j < 8; j++) { lw[j] = lnw[l + 32 * j]; lb[j] = lnb[l + 32 * j]; }
        for (int t = w; t < 128; t += 16) {
            float z[8];
            float s = 0.f, q = 0.f;
            #pragma unroll
            for (int j = 0; j < 8; j++) {
                z[j] = hs[HS(t, l + 32 * j)];
                s += z[j];
                q = fmaf(z[j], z[j], q);
            }
            #pragma unroll
            for (int off = 16; off; off >>= 1) {
                s += __shfl_xor_sync(0xFFFFFFFFu, s, off);
                q += __shfl_xor_sync(0xFFFFFFFFu, q, off);
            }
            float mean = s * (1.f / 256.f);
            float inv = rsqrtf(q * (1.f / 256.f) - mean * mean + EPSF);
            float* ob = out + ((size_t)(b * 128 + t) * 64 + n) * 256;
            #pragma unroll
            for (int j = 0; j < 8; j++) {
                float u = fmaf((z[j] - mean) * inv, lw[j], lb[j]);
                ob[l + 32 * j] = 0.5f * u * (1.f + erff(u * 0.70710678f));
            }
        }
    }
}

extern "C" void kernel_launch(void* const* d_in, const int* in_sizes, int n_in,
                              void* d_out, int out_size) {
    const float* x     = (const float*)d_in[0];
    const float* A     = (const float*)d_in[1];
    const float* dw    = (const float*)d_in[2];
    const float* Wpw   = (const float*)d_in[3];
    const float* Wconv = (const float*)d_in[4];
    const float* gnw   = (const float*)d_in[5];
    const float* gnb   = (const float*)d_in[6];
    const float* lnw   = (const float*)d_in[7];
    const float* lnb   = (const float*)d_in[8];
    const float* Wres  = (const float*)d_in[9];
    float* out = (float*)d_out;

    cudaFuncSetAttribute(k_main, cudaFuncAttributeMaxDynamicSharedMemorySize, 230400);

    k0_weights<<<dim3(64, 2), 256>>>(A, dw, Wpw, Wres);
    k_main<<<dim3(64, 16), 512, 230400>>>(x, Wconv, gnw, gnb, lnw, lnb, out);
}

// round 17
// speedup vs baseline: 1.6768x; 1.6768x over previous
#include <cuda_runtime.h>
#include <cuda_fp16.h>
#include <cstdint>

// Shapes: B=16, T=128, N=64, Cin=128, Cout=256, K=3, kt=3, groups=8
// Per-CTA (b,n): C[128 t][512 vcol] = X[128x128] @ W[n][vcol][c]^T, split-fp16, 2 K-sections
//   sharing one B image: D = x_hi*W_h + x_lo*W_h  (W_h = fp16(W); dropped x*W_lo ~ 2^-12 rel)
// vcol<256: h2 (pre-conv)   vcol>=256: residual
// g_Wh[n][vcol 512][k 128] fp16.  8 fused k32-chunks (pass = j>>2): j<4 -> hs, j>=4 -> regs,
// ONE accumulator array (flushed+rezeroed at j==3) to stay under the 128-reg budget.
// 512 threads / 16 warps: m0=(w>>2)*32 (2 m16 tiles); strip n0=(w&3)*64 (8 n8 tiles).

#define EPSF 1e-5f
#define HS(t,o) ((t)*256 + (((o) & ~31) | (((o) ^ (t)) & 31)))

__device__ __half g_Wh[64UL * 512 * 128];   // 8.4 MB fp16 weight image

// ---------------- helpers ----------------
__device__ __forceinline__ uint32_t s2u(const void* p) {
    uint32_t a;
    asm("{ .reg .u64 t; cvta.to.shared.u64 t, %1; cvt.u32.u64 %0, t; }" : "=r"(a) : "l"(p));
    return a;
}
__device__ __forceinline__ void ldmA(uint32_t* a, uint32_t addr) {
    asm volatile("ldmatrix.sync.aligned.m8n8.x4.shared.b16 {%0,%1,%2,%3}, [%4];"
                 : "=r"(a[0]), "=r"(a[1]), "=r"(a[2]), "=r"(a[3]) : "r"(addr));
}
__device__ __forceinline__ void ldmB4(uint32_t* q, uint32_t addr) {
    asm volatile("ldmatrix.sync.aligned.m8n8.x4.shared.b16 {%0,%1,%2,%3}, [%4];"
                 : "=r"(q[0]), "=r"(q[1]), "=r"(q[2]), "=r"(q[3]) : "r"(addr));
}
__device__ __forceinline__ void mma16816(float* c, const uint32_t* a, const uint32_t* bq) {
    asm volatile("mma.sync.aligned.m16n8k16.row.col.f32.f16.f16.f32 "
                 "{%0,%1,%2,%3}, {%4,%5,%6,%7}, {%8,%9}, {%0,%1,%2,%3};"
                 : "+f"(c[0]), "+f"(c[1]), "+f"(c[2]), "+f"(c[3])
                 : "r"(a[0]), "r"(a[1]), "r"(a[2]), "r"(a[3]), "r"(bq[0]), "r"(bq[1]));
}
__device__ __forceinline__ void cpa16(uint32_t dst, const void* src) {
    asm volatile("cp.async.cg.shared.global [%0], [%1], 16;"
                 :: "r"(dst), "l"((unsigned long long)__cvta_generic_to_global(src)));
}
#define CPA_COMMIT() asm volatile("cp.async.commit_group;" ::: "memory")
#define CPA_WAIT1()  asm volatile("cp.async.wait_group 1;" ::: "memory")
#define CPA_WAIT0()  asm volatile("cp.async.wait_group 0;" ::: "memory")

__device__ __forceinline__ uint32_t packh(float a, float b) {
    __half2 h = __floats2half2_rn(a, b);   // low half = a
    return *(uint32_t*)&h;
}

// ---------------- K0: build fp16 weight image ----------------
// Weff[n][v][c] = sum_k rowA[k,n]*dw[k,c]*Wpw[v,k*128+c]  (v<256);  Wres[v-256][c] (v>=256)
__global__ void k0_weights(const float* __restrict__ A, const float* __restrict__ dw,
                           const float* __restrict__ Wpw, const float* __restrict__ Wres) {
    int n = blockIdx.x;
    int vBase = blockIdx.y * 64;
    int tid = threadIdx.x;
    __shared__ float rA[3];
    if (tid < 3) {
        const float* Ap = A + (size_t)tid * 4096 + n * 64;
        float s = 0.f;
        #pragma unroll
        for (int m = 0; m < 64; m++) s += Ap[m];
        rA[tid] = s;
    }
    __syncthreads();
    float r0 = rA[0], r1 = rA[1], r2 = rA[2];
    uint32_t* dW = (uint32_t*)g_Wh + (size_t)n * 32768;

    for (int it = 0; it < 16; it++) {
        int idx = tid + it * 256;
        int c2 = idx & 63;
        int v = vBase + (idx >> 6);
        int c = c2 * 2;
        float wa, wb;
        if (v < 256) {
            wa = r0 * dw[c]       * Wpw[(size_t)v * 384 + c]
               + r1 * dw[128 + c] * Wpw[(size_t)v * 384 + 128 + c]
               + r2 * dw[256 + c] * Wpw[(size_t)v * 384 + 256 + c];
            wb = r0 * dw[c + 1]   * Wpw[(size_t)v * 384 + c + 1]
               + r1 * dw[129 + c] * Wpw[(size_t)v * 384 + 129 + c]
               + r2 * dw[257 + c] * Wpw[(size_t)v * 384 + 257 + c];
        } else {
            wa = Wres[(size_t)(v - 256) * 128 + c];
            wb = Wres[(size_t)(v - 256) * 128 + c + 1];
        }
        dW[v * 64 + c2] = packh(wa, wb);
    }
}

// ---------------- K_MAIN ----------------
// Dyn smem (1024-aligned): xhi[32K] | xlo[32K] | Bbuf0[16K] | Bbuf1[16K] | hs[128K] = 224KB
__global__ __launch_bounds__(512, 1) void k_main(
    const float* __restrict__ x, const float* __restrict__ Wconv,
    const float* __restrict__ gnw, const float* __restrict__ gnb,
    const float* __restrict__ lnw, const float* __restrict__ lnb,
    float* __restrict__ out)
{
    extern __shared__ char dyn[];
    __shared__ float redS[16], redQ[16], gmean[8], ginv[8];
    uint32_t dynBase = s2u(dyn);
    uint32_t base = (dynBase + 1023u) & ~1023u;
    char* smemc = dyn + (base - dynBase);
    float* hs = (float*)(smemc + 98304);

    int n = blockIdx.x, b = blockIdx.y;
    int tid = threadIdx.x;
    int w = tid >> 5, l = tid & 31;
    int m0 = (w >> 2) * 32;          // warp M origin: 2 m16 tiles
    int n0 = (w & 3) * 64;           // warp N strip: 8 n8 tiles

    const char* wimg = (const char*)g_Wh + (size_t)n * 131072;   // [512 v][256 B]

    // B buffer (16KB, 256 rows x 64B): boff(r) = (r>>1)*128 + (r&1)*64,
    // 16B chunk ch at + ((ch ^ ((r>>1)&3)) << 4).
    // fused chunk j (0..7): pass p=j>>2 (row offset p*256), k-chunk cj=j&3 (k32).
#define ISSUE_CHUNK(j) do {                                                             \
    const char* bsrc_ = wimg + (size_t)(((j) >> 2) * 256) * 256 + ((j) & 3) * 64;       \
    uint32_t dstb_ = base + 65536u + (uint32_t)((j) & 1) * 16384u;                      \
    _Pragma("unroll")                                                                   \
    for (int it_ = 0; it_ < 2; it_++) {                                                 \
        int flat_ = tid + it_ * 512;                                                    \
        int ch_ = flat_ & 3, r_ = flat_ >> 2;                                           \
        uint32_t d_ = dstb_ + (uint32_t)((r_ >> 1) * 128 + (r_ & 1) * 64)               \
                      + (uint32_t)(((ch_ ^ ((r_ >> 1) & 3))) << 4);                     \
        cpa16(d_, bsrc_ + (size_t)r_ * 256 + ch_ * 16);                                 \
    }                                                                                   \
    CPA_COMMIT();                                                                       \
} while (0)

    // Per k16: ldmA(hi) -> 4x ldmB4 -> 16 hi-MMAs -> ldmA(lo) -> 16 lo-MMAs (RAW dist >= 16).
#define COMPUTE_CHUNK(j, acc) do {                                                      \
    uint32_t bbase_ = base + 65536u + (uint32_t)((j) & 1) * 16384u;                     \
    _Pragma("unroll")                                                                   \
    for (int kk_ = 0; kk_ < 2; kk_++) {                                                 \
        int chA_ = ((j) & 3) * 4 + kk_ * 2 + (l >> 4);                                  \
        uint32_t af_[2][4];                                                             \
        _Pragma("unroll")                                                               \
        for (int mt_ = 0; mt_ < 2; mt_++) {                                             \
            int m_ = m0 + mt_ * 16 + (l & 15);                                          \
            ldmA(af_[mt_], base + (uint32_t)m_ * 256u + (uint32_t)((chA_ ^ (m_ & 7)) << 4)); \
        }                                                                               \
        uint32_t q_[4][4];                                                              \
        _Pragma("unroll")                                                               \
        for (int np_ = 0; np_ < 4; np_++) {                                             \
            int r_ = n0 + np_ * 16 + ((l >> 4) << 3) + (l & 7);                         \
            int chB_ = kk_ * 2 + ((l >> 3) & 1);                                        \
            ldmB4(q_[np_], bbase_ + (uint32_t)((r_ >> 1) * 128 + (r_ & 1) * 64)         \
                      + (uint32_t)(((chB_ ^ ((r_ >> 1) & 3))) << 4));                   \
        }                                                                               \
        _Pragma("unroll")                                                               \
        for (int np_ = 0; np_ < 4; np_++)                                               \
            _Pragma("unroll")                                                           \
            for (int mt_ = 0; mt_ < 2; mt_++) {                                         \
                mma16816(&(acc)[(mt_ * 8 + np_ * 2) * 4],     af_[mt_], q_[np_]);       \
                mma16816(&(acc)[(mt_ * 8 + np_ * 2 + 1) * 4], af_[mt_], q_[np_] + 2);   \
            }                                                                           \
        _Pragma("unroll")                                                               \
        for (int mt_ = 0; mt_ < 2; mt_++) {                                             \
            int m_ = m0 + mt_ * 16 + (l & 15);                                          \
            ldmA(af_[mt_], base + 32768u + (uint32_t)m_ * 256u + (uint32_t)((chA_ ^ (m_ & 7)) << 4)); \
        }                                                                               \
        _Pragma("unroll")                                                               \
        for (int np_ = 0; np_ < 4; np_++)                                               \
            _Pragma("unroll")                                                           \
            for (int mt_ = 0; mt_ < 2; mt_++) {                                         \
                mma16816(&(acc)[(mt_ * 8 + np_ * 2) * 4],     af_[mt_], q_[np_]);       \
                mma16816(&(acc)[(mt_ * 8 + np_ * 2 + 1) * 4], af_[mt_], q_[np_] + 2);   \
            }                                                                           \
    }                                                                                   \
} while (0)

#define ZERO64(a) { _Pragma("unroll") for (int z_ = 0; z_ < 64; z_++) (a)[z_] = 0.f; }
#define FLUSH_HS(acc) do {                                                              \
    _Pragma("unroll")                                                                   \
    for (int mt_ = 0; mt_ < 2; mt_++)                                                   \
    { _Pragma("unroll")                                                                 \
      for (int nt_ = 0; nt_ < 8; nt_++) {                                               \
        int t_ = m0 + mt_ * 16 + (l >> 2);                                              \
        int o_ = n0 + nt_ * 8 + (l & 3) * 2;                                            \
        int i4_ = (mt_ * 8 + nt_) * 4;                                                  \
        hs[HS(t_, o_)]         = (acc)[i4_ + 0];                                        \
        hs[HS(t_, o_ + 1)]     = (acc)[i4_ + 1];                                        \
        hs[HS(t_ + 8, o_)]     = (acc)[i4_ + 2];                                        \
        hs[HS(t_ + 8, o_ + 1)] = (acc)[i4_ + 3];                                        \
    } }                                                                                 \
} while (0)

    // ---- chunk 0 cp.async in flight BEFORE the x-split (overlap) ----
    ISSUE_CHUNK(0);

    // ---- load x tile [128 t][128 c], split hi/lo fp16, XOR-swizzled 256B rows ----
    {
        int cq = tid & 31, tr = tid >> 5;  // tr 0..15
        const float* xb = x + (size_t)b * 1048576 + (size_t)n * 128;
        #pragma unroll
        for (int i = 0; i < 8; i++) {
            int t = tr + i * 16;
            float4 v = *(const float4*)(xb + (size_t)t * 8192 + cq * 4);
            float hx = __half2float(__float2half_rn(v.x));
            float hy = __half2float(__float2half_rn(v.y));
            float hz = __half2float(__float2half_rn(v.z));
            float hw = __half2float(__float2half_rn(v.w));
            uint32_t h0 = packh(v.x, v.y), h1 = packh(v.z, v.w);
            uint32_t l0 = packh(v.x - hx, v.y - hy), l1 = packh(v.z - hz, v.w - hw);
            int ch = cq >> 1;
            uint32_t off = (uint32_t)t * 256u + (uint32_t)((ch ^ (t & 7)) << 4) + (uint32_t)((cq & 1) * 8);
            *(uint64_t*)(smemc + off)         = (uint64_t)h0 | ((uint64_t)h1 << 32);
            *(uint64_t*)(smemc + 32768 + off) = (uint64_t)l0 | ((uint64_t)l1 << 32);
        }
    }
    __syncthreads();   // A (xhi/xlo) visible to all warps
    ISSUE_CHUNK(1);

    // ---- fused 8-chunk pipeline, ONE accumulator array ----
    // j<4: h2 accumulation; at j==3 flush to hs and re-zero; j>=4: residual accumulation.
    float acc[64];
    ZERO64(acc);
    #pragma unroll
    for (int j = 0; j < 8; j++) {
        if (j < 7) CPA_WAIT1(); else CPA_WAIT0();
        __syncthreads();                 // B chunk j ready for all warps
        COMPUTE_CHUNK(j, acc);
        if (j == 3) { FLUSH_HS(acc); ZERO64(acc); }   // warp-private hs region
        __syncthreads();                 // all warps done with buffer (j&1)
        if (j < 6) ISSUE_CHUNK(j + 2);
    }
    __syncthreads();

    // ---- E1: depthwise conv3 over T + GroupNorm. thread = (channel o, t-half h). ----
    {
        int o = tid & 255, h = tid >> 8, t0 = h * 64;
        float cw0 = Wconv[o * 3], cw1 = Wconv[o * 3 + 1], cw2 = Wconv[o * 3 + 2];
        float lf = (t0 > 0) ? hs[HS(t0 - 1, o)] : 0.f;
        float endrt = (t0 + 64 < 128) ? hs[HS(t0 + 64, o)] : 0.f;
        float cur = hs[HS(t0, o)];
        __syncthreads();
        float s = 0.f, q = 0.f;
        #pragma unroll 4
        for (int i = 0; i < 64; i++) {
            int t = t0 + i;
            float rt = (i < 63) ? hs[HS(t + 1, o)] : endrt;
            float val = fmaf(cw0, lf, fmaf(cw1, cur, cw2 * rt));
            hs[HS(t, o)] = val;
            s += val;
            q = fmaf(val, val, q);
            lf = cur; cur = rt;
        }
        #pragma unroll
        for (int off = 16; off; off >>= 1) {
            s += __shfl_xor_sync(0xFFFFFFFFu, s, off);
            q += __shfl_xor_sync(0xFFFFFFFFu, q, off);
        }
        if (l == 0) { redS[w] = s; redQ[w] = q; }
        __syncthreads();
        if (tid < 8) {
            float S2 = redS[tid] + redS[tid + 8];
            float Q2 = redQ[tid] + redQ[tid + 8];
            float mean = S2 * (1.f / 4096.f);
            float var = Q2 * (1.f / 4096.f) - mean * mean;
            gmean[tid] = mean;
            ginv[tid] = rsqrtf(var + EPSF);
        }
        __syncthreads();
        int g = o >> 5;
        float sc = ginv[g] * gnw[o];
        float sb = gnb[o] - gmean[g] * sc;
        #pragma unroll 4
        for (int i = 0; i < 64; i++) {
            int t = t0 + i;
            hs[HS(t, o)] = fmaf(hs[HS(t, o)], sc, sb);
        }
    }
    __syncthreads();

    // ---- E2: add residual from registers (acc holds residual after j>=4) ----
    #pragma unroll
    for (int mt = 0; mt < 2; mt++)
        #pragma unroll
        for (int nt = 0; nt < 8; nt++) {
            int t = m0 + mt * 16 + (l >> 2);
            int o = n0 + nt * 8 + (l & 3) * 2;
            int i4 = (mt * 8 + nt) * 4;
            hs[HS(t, o)]         += acc[i4 + 0];
            hs[HS(t, o + 1)]     += acc[i4 + 1];
            hs[HS(t + 8, o)]     += acc[i4 + 2];
            hs[HS(t + 8, o + 1)] += acc[i4 + 3];
        }
    __syncthreads();

    // ---- E3: LayerNorm over 256 channels per t-row + exact GELU + coalesced store ----
    {
        float lw[8], lb[8];
        #pragma unroll
        for (int j = 0; j < 8; j++) { lw[j] = lnw[l + 32 * j]; lb[j] = lnb[l + 32 * j]; }
        for (int t = w; t < 128; t += 16) {
            float z[8];
            float s = 0.f, q = 0.f;
            #pragma unroll
            for (int j = 0; j < 8; j++) {
                z[j] = hs[HS(t, l + 32 * j)];
                s += z[j];
                q = fmaf(z[j], z[j], q);
            }
            #pragma unroll
            for (int off = 16; off; off >>= 1) {
                s += __shfl_xor_sync(0xFFFFFFFFu, s, off);
                q += __shfl_xor_sync(0xFFFFFFFFu, q, off);
            }
            float mean = s * (1.f / 256.f);
            float inv = rsqrtf(q * (1.f / 256.f) - mean * mean + EPSF);
            float* ob = out + ((size_t)(b * 128 + t) * 64 + n) * 256;
            #pragma unroll
            for (int j = 0; j < 8; j++) {
                float u = fmaf((z[j] - mean) * inv, lw[j], lb[j]);
                ob[l + 32 * j] = 0.5f * u * (1.f + erff(u * 0.70710678f));
            }
        }
    }
}

extern "C" void kernel_launch(void* const* d_in, const int* in_sizes, int n_in,
                              void* d_out, int out_size) {
    const float* x     = (const float*)d_in[0];
    const float* A     = (const float*)d_in[1];
    const float* dw    = (const float*)d_in[2];
    const float* Wpw   = (const float*)d_in[3];
    const float* Wconv = (const float*)d_in[4];
    const float* gnw   = (const float*)d_in[5];
    const float* gnb   = (const float*)d_in[6];
    const float* lnw   = (const float*)d_in[7];
    const float* lnb   = (const float*)d_in[8];
    const float* Wres  = (const float*)d_in[9];
    float* out = (float*)d_out;

    cudaFuncSetAttribute(k_main, cudaFuncAttributeMaxDynamicSharedMemorySize, 230400);

    k0_weights<<<dim3(64, 8), 256>>>(A, dw, Wpw, Wres);
    k_main<<<dim3(64, 16), 512, 230400>>>(x, Wconv, gnw, gnb, lnw, lnb, out);
}